// round 9
// baseline (speedup 1.0000x reference)
#include <cuda_runtime.h>
#include <cuda_fp16.h>
#include <cstdint>

#define NN 2048
#define MMT 2048
#define WARPS 14
#define THREADS (WARPS * 32)
#define GRID 147
#define TILE_MB 16
#define HRW 34           // hrh m-row stride in 4B words (bank-verified, even)

__device__ __forceinline__ float tanh_ap(float x) {
    float y; asm("tanh.approx.f32 %0, %1;" : "=f"(y) : "f"(x)); return y;
}
__device__ __forceinline__ uint32_t pack_h2(float lo, float hi) {
    uint32_t u; asm("cvt.rn.f16x2.f32 %0, %1, %2;" : "=r"(u) : "f"(hi), "f"(lo)); return u;
}
__device__ __forceinline__ uint32_t h2add(uint32_t a, uint32_t b) {
    uint32_t d; asm("add.rn.f16x2 %0, %1, %2;" : "=r"(d) : "r"(a), "r"(b)); return d;
}
__device__ __forceinline__ uint32_t h2fma(uint32_t a, uint32_t b, uint32_t c) {
    uint32_t d; asm("fma.rn.f16x2 %0, %1, %2, %3;" : "=r"(d) : "r"(a), "r"(b), "r"(c)); return d;
}
__device__ __forceinline__ uint32_t h2tanh(uint32_t a) {
    uint32_t d; asm("tanh.approx.f16x2 %0, %1;" : "=r"(d) : "r"(a)); return d;
}
__device__ __forceinline__ float2 h22f2(uint32_t u) {
    float2 f;
    asm("{ .reg .b16 lo, hi; mov.b32 {lo, hi}, %2; cvt.f32.f16 %0, lo; cvt.f32.f16 %1, hi; }"
        : "=f"(f.x), "=f"(f.y) : "r"(u));
    return f;
}
__device__ __forceinline__ void mma_k8h(uint32_t& d0, uint32_t& d1,
                                        uint32_t a0, uint32_t a1, uint32_t b0) {
    asm volatile(
        "mma.sync.aligned.m16n8k8.row.col.f16.f16.f16.f16 "
        "{%0,%1}, {%2,%3}, {%4}, {%0,%1};"
        : "+r"(d0), "+r"(d1) : "r"(a0), "r"(a1), "r"(b0));
}
__device__ __forceinline__ void mma_k16h(uint32_t& d0, uint32_t& d1,
                                         uint32_t a0, uint32_t a1, uint32_t a2, uint32_t a3,
                                         uint32_t b0, uint32_t b1) {
    asm volatile(
        "mma.sync.aligned.m16n8k16.row.col.f16.f16.f16.f16 "
        "{%0,%1}, {%2,%3,%4,%5}, {%6,%7}, {%0,%1};"
        : "+r"(d0), "+r"(d1)
        : "r"(a0), "r"(a1), "r"(a2), "r"(a3), "r"(b0), "r"(b1));
}

// word offset within an hrh row for channel-pair p (p = c/2; c = nt*8+2q)
__device__ __forceinline__ int pair_off(int p) {
    return (p & 3) * 8 + ((p >> 3) << 1) + ((p >> 2) & 1);
}

// ---------------------------------------------------------------------------
// Fully fused, single kernel. Grid 147 x 448, warp w owns node blockIdx*14+w.
// All weights pre-scaled by 0.5 so MMA outputs land directly in tanh space:
//   MMA1 -> hp = 0.5*pre; silu = fma(hp, tanh(hp), hp)
//   MMA2 -> 0.5*E;        t    = tanh(0.5E + 0.5b2)
// Accumulate t*h in f16x2 (4-chunk flush) and t in f16x2 (8-chunk flush).
// sumH computed in-CTA from the chunk stream. Node MLP fused tail.
// ---------------------------------------------------------------------------
__global__ void __launch_bounds__(THREADS, 1)
fused_kernel(const float* __restrict__ h_l, const float* __restrict__ x_l,
             const float* __restrict__ h_r, const float* __restrict__ x_r,
             const float* __restrict__ W1, const float* __restrict__ b1,
             const float* __restrict__ W2, const float* __restrict__ b2,
             const float* __restrict__ Wn1, const float* __restrict__ bn1,
             const float* __restrict__ ln_g, const float* __restrict__ ln_b,
             const float* __restrict__ Wn2, const float* __restrict__ bn2,
             float* __restrict__ out)
{
    __shared__ uint4 b4p[2][8][32];           // 0.5*W2 frags, lane-indexed
    __shared__ uint32_t hrh[2][16 * HRW];     // h_r chunk as f16x2 channel-pairs
    __shared__ float xrs[2][48];
    __shared__ float rps[2][48];
    __shared__ float hsum_s[16][68];
    __shared__ float sumH_s[64];
    __shared__ float hagg_s[WARPS][64];
    __shared__ float ss_s[WARPS][64];

    const int tid  = threadIdx.x;
    const int w    = tid >> 5;
    const int lane = tid & 31;
    const int r    = lane >> 2;
    const int q    = lane & 3;

    // ---- one-time: 0.5*W2 fragments for consumer lane l = (r=l>>2, q=l&3) ----
    for (int i = tid; i < 512; i += THREADS) {
        int l  = i & 31, nt = (i >> 5) & 7, kp = i >> 8;
        int rr = l >> 2, qq = l & 3;
        int c  = nt * 8 + rr;
        uint4 v;
        {
            int j0 = (2 * kp) * 16 + 2 * qq;
            v.x = pack_h2(0.5f * W2[j0 * 64 + c],       0.5f * W2[(j0 + 1) * 64 + c]);
            v.y = pack_h2(0.5f * W2[(j0 + 8) * 64 + c], 0.5f * W2[(j0 + 9) * 64 + c]);
        }
        {
            int j0 = (2 * kp + 1) * 16 + 2 * qq;
            v.z = pack_h2(0.5f * W2[j0 * 64 + c],       0.5f * W2[(j0 + 1) * 64 + c]);
            v.w = pack_h2(0.5f * W2[(j0 + 8) * 64 + c], 0.5f * W2[(j0 + 9) * 64 + c]);
        }
        b4p[kp][nt][l] = v;
    }
    // ---- one-time: 0.5*W1 B-fragments (registers) ----
    uint32_t b1f[8];
    #pragma unroll
    for (int nt = 0; nt < 8; nt++) {
        int cc = nt * 8 + r;
        b1f[nt] = (q == 0) ? pack_h2(0.5f * W1[cc], 0.5f * W1[64 + cc])
                : (q == 1) ? pack_h2(0.5f * W1[128 + cc], 0.5f * (W1[192 + cc] + b1[cc]))
                : 0u;
    }
    // ---- one-time: 0.5*b2 as half2 per nt ----
    uint32_t hb2h[8];
    #pragma unroll
    for (int nt = 0; nt < 8; nt++) {
        int c0 = nt * 8 + 2 * q;
        hb2h[nt] = pack_h2(0.5f * b2[c0], 0.5f * b2[c0 + 1]);
    }

    // per-warp n-row invariants (clamped for the ragged last CTA)
    int nrow = blockIdx.x * WARPS + w;
    if (nrow > NN - 1) nrow = NN - 1;
    const float xlx = x_l[nrow * 3 + 0];
    const float xly = x_l[nrow * 3 + 1];
    const float xlz = x_l[nrow * 3 + 2];
    const float l0  = h_l[nrow * 64 + 61];
    const float l1  = h_l[nrow * 64 + 62];
    const float l2  = h_l[nrow * 64 + 63];

    const int mi0 = r, mi1 = r + 8;

    float accF[16], swaf[16];
    uint32_t accH[8], sswa[8];
    #pragma unroll
    for (int i = 0; i < 16; i++) { accF[i] = 0.f; swaf[i] = 0.f; }
    #pragma unroll
    for (int i = 0; i < 8; i++) { accH[i] = 0u; sswa[i] = 0u; }

    // loader thread identity (tid < 256): row mm, channel-quad k
    const int mm_ld = tid >> 4, k_ld = tid & 15;
    const int off0 = pair_off(2 * k_ld);
    const int off1 = pair_off(2 * k_ld + 1);
    float4 hsum = make_float4(0.f, 0.f, 0.f, 0.f);

    #define LOAD_CHUNK(m0_, buf_) do {                                          \
        if (tid < 48) xrs[buf_][tid] = x_r[(m0_) * 3 + tid];                    \
        else if (tid < 96) {                                                    \
            int t = tid - 48;                                                   \
            rps[buf_][t] = h_r[((m0_) + t / 3) * 64 + 61 + t % 3];              \
        }                                                                       \
        if (tid < 256) {                                                        \
            float4 v = ((const float4*)(h_r + (m0_) * 64))[tid];                \
            hsum.x += v.x; hsum.y += v.y; hsum.z += v.z; hsum.w += v.w;         \
            uint32_t* dst = &hrh[buf_][mm_ld * HRW];                            \
            dst[off0] = pack_h2(v.x, v.y);                                      \
            dst[off1] = pack_h2(v.z, v.w);                                      \
        }                                                                       \
    } while (0)

    LOAD_CHUNK(0, 0);
    int buf = 0;

    for (int chunk = 0; chunk < MMT / TILE_MB; chunk++) {
        __syncthreads();
        if (chunk + 1 < MMT / TILE_MB) LOAD_CHUNK((chunk + 1) * TILE_MB, buf ^ 1);

        const float* xr = xrs[buf];
        const float* rp = rps[buf];
        const uint32_t* hp0 = &hrh[buf][mi0 * HRW + q * 8];
        const uint32_t* hp1 = &hrh[buf][mi1 * HRW + q * 8];

        // ---- edge scalars for this lane's two m-rows ----
        float a0v, bh0, ch0, a1v, bh1, ch1;
        {
            float dx = xlx - xr[mi0 * 3 + 0];
            float dy = xly - xr[mi0 * 3 + 1];
            float dz = xlz - xr[mi0 * 3 + 2];
            float d2 = fmaf(dx, dx, fmaf(dy, dy, dz * dz));
            a0v = __expf(-0.2f * d2);
            bh0 = fmaf(l0, rp[mi0 * 3 + 1], l1 * rp[mi0 * 3 + 0]);
            ch0 = l2 * rp[mi0 * 3 + 2];
        }
        {
            float dx = xlx - xr[mi1 * 3 + 0];
            float dy = xly - xr[mi1 * 3 + 1];
            float dz = xlz - xr[mi1 * 3 + 2];
            float d2 = fmaf(dx, dx, fmaf(dy, dy, dz * dz));
            a1v = __expf(-0.2f * d2);
            bh1 = fmaf(l0, rp[mi1 * 3 + 1], l1 * rp[mi1 * 3 + 0]);
            ch1 = l2 * rp[mi1 * 3 + 2];
        }

        // ---- ER A-fragments for MMA1 ----
        float e00 = (q == 0) ? a0v : (q == 1) ? ch0 : 0.f;
        float e01 = (q == 0) ? bh0 : (q == 1) ? 1.f : 0.f;
        float e10 = (q == 0) ? a1v : (q == 1) ? ch1 : 0.f;
        float e11 = (q == 0) ? bh1 : (q == 1) ? 1.f : 0.f;
        uint32_t A10 = pack_h2(e00, e01);
        uint32_t A11 = pack_h2(e10, e11);

        // ---- MMA1 (0.5-scaled) + silu: A2 = fma(hp, tanh(hp), hp) ----
        uint32_t A2[4][4];
        #pragma unroll
        for (int kt = 0; kt < 4; kt++) {
            uint32_t p00 = 0u, p01 = 0u, p10 = 0u, p11 = 0u;
            mma_k8h(p00, p01, A10, A11, b1f[2 * kt]);
            mma_k8h(p10, p11, A10, A11, b1f[2 * kt + 1]);
            A2[kt][0] = h2fma(p00, h2tanh(p00), p00);
            A2[kt][1] = h2fma(p01, h2tanh(p01), p01);
            A2[kt][2] = h2fma(p10, h2tanh(p10), p10);
            A2[kt][3] = h2fma(p11, h2tanh(p11), p11);
        }

        // ---- MMA2 (0.5-scaled) + tanh + f16x2 accumulate ----
        #pragma unroll
        for (int np = 0; np < 4; np++) {
            uint2 H0 = *(const uint2*)(hp0 + np * 2);   // pairs for nt=2np, 2np+1, row mi0
            uint2 H1 = *(const uint2*)(hp1 + np * 2);   // same, row mi1
            #pragma unroll
            for (int s = 0; s < 2; s++) {
                const int nt = np * 2 + s;
                uint32_t D01 = 0u, D23 = 0u;
                uint4 B0 = b4p[0][nt][lane];
                uint4 B1 = b4p[1][nt][lane];
                mma_k16h(D01, D23, A2[0][0], A2[0][1], A2[0][2], A2[0][3], B0.x, B0.y);
                mma_k16h(D01, D23, A2[1][0], A2[1][1], A2[1][2], A2[1][3], B0.z, B0.w);
                mma_k16h(D01, D23, A2[2][0], A2[2][1], A2[2][2], A2[2][3], B1.x, B1.y);
                mma_k16h(D01, D23, A2[3][0], A2[3][1], A2[3][2], A2[3][3], B1.z, B1.w);

                uint32_t t01 = h2tanh(h2add(D01, hb2h[nt]));   // row mi0, (c0,c1)
                uint32_t t23 = h2tanh(h2add(D23, hb2h[nt]));   // row mi1
                uint32_t h0 = s ? H0.y : H0.x;
                uint32_t h1 = s ? H1.y : H1.x;
                accH[nt] = h2fma(t01, h0, accH[nt]);
                accH[nt] = h2fma(t23, h1, accH[nt]);
                sswa[nt] = h2add(sswa[nt], h2add(t01, t23));
            }
        }
        // ---- flushes: acc every 4 chunks, swa every 8 ----
        if ((chunk & 3) == 3) {
            #pragma unroll
            for (int nt = 0; nt < 8; nt++) {
                float2 a = h22f2(accH[nt]);
                accF[nt * 2 + 0] += a.x;
                accF[nt * 2 + 1] += a.y;
                accH[nt] = 0u;
            }
        }
        if ((chunk & 7) == 7) {
            #pragma unroll
            for (int nt = 0; nt < 8; nt++) {
                float2 s = h22f2(sswa[nt]);
                swaf[nt * 2 + 0] += s.x;
                swaf[nt * 2 + 1] += s.y;
                sswa[nt] = 0u;
            }
        }
        buf ^= 1;
    }

    // ---- in-CTA sumH reduce: hsum per (mm, quad) -> sumH_s[64] ----
    __syncthreads();
    if (tid < 256) *(float4*)&hsum_s[mm_ld][4 * k_ld] = hsum;
    __syncthreads();
    if (tid < 64) {
        float s = 0.f;
        #pragma unroll
        for (int m = 0; m < 16; m++) s += hsum_s[m][tid];
        sumH_s[tid] = s;
    }
    __syncthreads();

    // ---- reduce over r-groups, form h_agg ----
    #pragma unroll
    for (int j = 0; j < 16; j++) {
        #pragma unroll
        for (int off = 4; off <= 16; off <<= 1) {
            accF[j] += __shfl_xor_sync(0xffffffffu, accF[j], off);
            swaf[j] += __shfl_xor_sync(0xffffffffu, swaf[j], off);
        }
    }
    if (lane < 4) {      // r == 0, q = lane
        #pragma unroll
        for (int nt = 0; nt < 8; nt++) {
            int c0 = nt * 8 + 2 * q;
            float num0 = fmaf(0.5f, accF[nt * 2 + 0], 0.5f * sumH_s[c0]);
            float num1 = fmaf(0.5f, accF[nt * 2 + 1], 0.5f * sumH_s[c0 + 1]);
            float den0 = fmaf(0.5f, swaf[nt * 2 + 0], 1024.0f + 1e-6f);
            float den1 = fmaf(0.5f, swaf[nt * 2 + 1], 1024.0f + 1e-6f);
            hagg_s[w][c0]     = num0 / den0;
            hagg_s[w][c0 + 1] = num1 / den1;
        }
    }
    __syncwarp();

    // ==== node MLP tail: warp w = node nrow; lane owns channels 2*lane, 2*lane+1 ====
    {
        const int k0 = 2 * lane;
        float2 bn1v = *(const float2*)&bn1[k0];
        float z0 = bn1v.x, z1 = bn1v.y;
        #pragma unroll 8
        for (int i = 0; i < 64; i++) {
            float hv = h_l[nrow * 64 + i];
            float2 wv = *(const float2*)&Wn1[i * 64 + k0];
            z0 = fmaf(hv, wv.x, z0);
            z1 = fmaf(hv, wv.y, z1);
        }
        #pragma unroll 8
        for (int i = 0; i < 64; i++) {
            float hv = hagg_s[w][i];
            float2 wv = *(const float2*)&Wn1[(64 + i) * 64 + k0];
            z0 = fmaf(hv, wv.x, z0);
            z1 = fmaf(hv, wv.y, z1);
        }
        float s = z0 + z1;
        #pragma unroll
        for (int off = 16; off >= 1; off >>= 1) s += __shfl_xor_sync(0xffffffffu, s, off);
        float mu = s * (1.0f / 64.0f);
        float d0 = z0 - mu, d1 = z1 - mu;
        float v = fmaf(d0, d0, d1 * d1);
        #pragma unroll
        for (int off = 16; off >= 1; off >>= 1) v += __shfl_xor_sync(0xffffffffu, v, off);
        float rstd = rsqrtf(v * (1.0f / 64.0f) + 1e-5f);

        float2 gv = *(const float2*)&ln_g[k0];
        float2 bv = *(const float2*)&ln_b[k0];
        float zn0 = fmaf(d0 * rstd, gv.x, bv.x);
        float zn1 = fmaf(d1 * rstd, gv.y, bv.y);
        float hp0 = 0.5f * zn0, hp1 = 0.5f * zn1;
        ss_s[w][k0]     = fmaf(hp0, tanh_ap(hp0), hp0);
        ss_s[w][k0 + 1] = fmaf(hp1, tanh_ap(hp1), hp1);
        __syncwarp();

        float2 bn2v = *(const float2*)&bn2[k0];
        float o0 = bn2v.x, o1 = bn2v.y;
        #pragma unroll 8
        for (int i = 0; i < 64; i++) {
            float sv = ss_s[w][i];
            float2 wv = *(const float2*)&Wn2[i * 64 + k0];
            o0 = fmaf(sv, wv.x, o0);
            o1 = fmaf(sv, wv.y, o1);
        }
        float2 hlv = *(const float2*)&h_l[nrow * 64 + k0];
        float2 ov;
        ov.x = hlv.x + o0;
        ov.y = hlv.y + o1;
        *(float2*)&out[nrow * 64 + k0] = ov;
    }
}

extern "C" void kernel_launch(void* const* d_in, const int* in_sizes, int n_in,
                              void* d_out, int out_size)
{
    const float* h_l  = (const float*)d_in[0];
    const float* x_l  = (const float*)d_in[1];
    const float* h_r  = (const float*)d_in[2];
    const float* x_r  = (const float*)d_in[3];
    const float* W1   = (const float*)d_in[4];
    const float* b1   = (const float*)d_in[5];
    const float* W2   = (const float*)d_in[6];
    const float* b2   = (const float*)d_in[7];
    const float* Wn1  = (const float*)d_in[8];
    const float* bn1  = (const float*)d_in[9];
    const float* ln_g = (const float*)d_in[10];
    const float* ln_b = (const float*)d_in[11];
    const float* Wn2  = (const float*)d_in[12];
    const float* bn2  = (const float*)d_in[13];
    float* out = (float*)d_out;

    fused_kernel<<<GRID, THREADS>>>(h_l, x_l, h_r, x_r, W1, b1, W2, b2,
                                    Wn1, bn1, ln_g, ln_b, Wn2, bn2, out);
}